// round 1
// baseline (speedup 1.0000x reference)
#include <cuda_runtime.h>
#include <math.h>
#include <stdint.h>

#define BATCH 65536
#define DIN   512
#define DOUT  512
#define HIDN  1024

// ---------------- scratch (static device globals; no allocation) -------------
__device__ float g_buf [(size_t)BATCH * DIN];   // evolving x / x_cms
__device__ float g_h   [(size_t)BATCH * HIDN];  // cms hidden, then gate-sigmoid sum
__device__ float g_slow[(size_t)BATCH * DOUT];
__device__ float g_fast[(size_t)BATCH * DOUT];
__device__ float g_gates[(size_t)BATCH * 3];
__device__ float g_hebb[DOUT * DIN];            // split-K accumulator (sum over b)
__device__ float g_m2  [DOUT];                  // sum_b fast^2
__device__ float g_stats[4];                    // sums of metab/sens/gate

__device__ __forceinline__ float sigf(float x) { return 1.0f / (1.0f + expf(-x)); }

// ---------------- zero accumulators ------------------------------------------
__global__ void zero_kernel() {
    int idx = blockIdx.x * blockDim.x + threadIdx.x;
    int stride = gridDim.x * blockDim.x;
    for (int i = idx; i < DOUT * DIN; i += stride) g_hebb[i] = 0.0f;
    if (idx < DOUT) g_m2[idx] = 0.0f;
    if (idx < 4)    g_stats[idx] = 0.0f;
}

// ---------------- generic C[b,n] = epi(A[b,:] . W[n,:] + bias[n]) ------------
enum { EPI_RELU = 0, EPI_RESID = 1, EPI_SIGW = 2, EPI_SIGA = 3, EPI_NONE = 4 };

template <int EPI>
__global__ __launch_bounds__(256)
void gemm_kernel(const float* __restrict__ A, const float* __restrict__ W,
                 const float* __restrict__ bias, const float* __restrict__ R,
                 float* __restrict__ C, int N, int K,
                 const int* __restrict__ step, int freq)
{
    if (freq > 1) { if ((step[0] % freq) != 0) return; }

    __shared__ float As[16][132];
    __shared__ float Bs[16][132];

    const int tid = threadIdx.x;
    const int m0 = blockIdx.y * 128;
    const int n0 = blockIdx.x * 128;
    const int tx = tid & 15;
    const int ty = tid >> 4;

    float acc[8][8];
#pragma unroll
    for (int i = 0; i < 8; ++i)
#pragma unroll
        for (int j = 0; j < 8; ++j) acc[i][j] = 0.0f;

    const int lr = tid >> 2;         // 0..63
    const int lc = (tid & 3) * 4;    // 0,4,8,12
    const float* Ag = A + (size_t)m0 * K + lc;
    const float* Wg = W + (size_t)n0 * K + lc;

    for (int k0 = 0; k0 < K; k0 += 16) {
#pragma unroll 2
        for (int rr = lr; rr < 128; rr += 64) {
            float4 va = *(const float4*)(Ag + (size_t)rr * K + k0);
            As[lc + 0][rr] = va.x; As[lc + 1][rr] = va.y;
            As[lc + 2][rr] = va.z; As[lc + 3][rr] = va.w;
            float4 vb = *(const float4*)(Wg + (size_t)rr * K + k0);
            Bs[lc + 0][rr] = vb.x; Bs[lc + 1][rr] = vb.y;
            Bs[lc + 2][rr] = vb.z; Bs[lc + 3][rr] = vb.w;
        }
        __syncthreads();
#pragma unroll
        for (int k = 0; k < 16; ++k) {
            float a[8], b[8];
            *(float4*)(a)     = *(const float4*)&As[k][ty * 8];
            *(float4*)(a + 4) = *(const float4*)&As[k][ty * 8 + 4];
            *(float4*)(b)     = *(const float4*)&Bs[k][tx * 8];
            *(float4*)(b + 4) = *(const float4*)&Bs[k][tx * 8 + 4];
#pragma unroll
            for (int i = 0; i < 8; ++i)
#pragma unroll
                for (int j = 0; j < 8; ++j)
                    acc[i][j] = fmaf(a[i], b[j], acc[i][j]);
        }
        __syncthreads();
    }

#pragma unroll
    for (int i = 0; i < 8; ++i) {
        const int m = m0 + ty * 8 + i;
#pragma unroll
        for (int j = 0; j < 8; ++j) {
            const int n = n0 + tx * 8 + j;
            const size_t idx = (size_t)m * N + n;
            float v = acc[i][j];
            if (EPI != EPI_NONE) v += bias[n];
            if      (EPI == EPI_RELU)  C[idx] = v > 0.0f ? v : 0.0f;
            else if (EPI == EPI_RESID) C[idx] = v + R[idx];
            else if (EPI == EPI_SIGW)  C[idx] = sigf(v);
            else if (EPI == EPI_SIGA)  C[idx] += sigf(v);
            else                       C[idx] = v;
        }
    }
}

// ---------------- gates head: B x 1024 -> B x 3 (+ stats sums) ---------------
__global__ __launch_bounds__(256)
void gateout_kernel(const float* __restrict__ gsum,
                    const float* __restrict__ w,   // [3][1024]
                    const float* __restrict__ b3)  // [3]
{
    __shared__ float sw[3 * HIDN];
    __shared__ float sacc[3];
    const int tid = threadIdx.x;
    for (int i = tid; i < 3 * HIDN; i += 256) sw[i] = w[i];
    if (tid < 3) sacc[tid] = 0.0f;
    __syncthreads();

    const int lane = tid & 31, warp = tid >> 5;
    const int b = blockIdx.x * 8 + warp;
    const float* row = gsum + (size_t)b * HIDN;
    float a0 = 0.f, a1 = 0.f, a2 = 0.f;
    for (int h = lane; h < HIDN; h += 32) {
        float v = row[h];
        a0 = fmaf(v, sw[h],            a0);
        a1 = fmaf(v, sw[HIDN + h],     a1);
        a2 = fmaf(v, sw[2 * HIDN + h], a2);
    }
#pragma unroll
    for (int o = 16; o > 0; o >>= 1) {
        a0 += __shfl_down_sync(0xffffffffu, a0, o);
        a1 += __shfl_down_sync(0xffffffffu, a1, o);
        a2 += __shfl_down_sync(0xffffffffu, a2, o);
    }
    if (lane == 0) {
        float s0 = sigf(a0 + b3[0]);
        float s1 = sigf(a1 + b3[1]);
        float s2 = sigf(a2 + b3[2]);
        g_gates[(size_t)b * 3 + 0] = s0;
        g_gates[(size_t)b * 3 + 1] = s1;
        g_gates[(size_t)b * 3 + 2] = s2;
        atomicAdd(&sacc[0], s0);
        atomicAdd(&sacc[1], s1);
        atomicAdd(&sacc[2], s2);
    }
    __syncthreads();
    if (tid < 3) atomicAdd(&g_stats[tid], sacc[tid]);
}

// ---------------- hebb: acc[o,d] += sum_b fast[b,o] * x_cms[b,d] (split-K) ---
__global__ __launch_bounds__(256)
void hebb_kernel()
{
    __shared__ float Fs[32][64];
    __shared__ float Xs[32][64];
    const int tid = threadIdx.x;
    const int o0 = blockIdx.x * 64;
    const int d0 = blockIdx.y * 64;
    const int b0 = blockIdx.z * 512;
    const int tx = tid & 15;
    const int ty = tid >> 4;

    float acc[4][4];
#pragma unroll
    for (int i = 0; i < 4; ++i)
#pragma unroll
        for (int j = 0; j < 4; ++j) acc[i][j] = 0.0f;

    const int lr = tid >> 4;        // 0..15
    const int lc = (tid & 15) * 4;  // 0..60

    for (int bt = 0; bt < 512; bt += 32) {
#pragma unroll 2
        for (int rr = lr; rr < 32; rr += 16) {
            const int b = b0 + bt + rr;
            *(float4*)&Fs[rr][lc] = *(const float4*)&g_fast[(size_t)b * DOUT + o0 + lc];
            *(float4*)&Xs[rr][lc] = *(const float4*)&g_buf [(size_t)b * DIN  + d0 + lc];
        }
        __syncthreads();
#pragma unroll
        for (int k = 0; k < 32; ++k) {
            float a[4], bb[4];
            *(float4*)a  = *(const float4*)&Fs[k][ty * 4];
            *(float4*)bb = *(const float4*)&Xs[k][tx * 4];
#pragma unroll
            for (int i = 0; i < 4; ++i)
#pragma unroll
                for (int j = 0; j < 4; ++j)
                    acc[i][j] = fmaf(a[i], bb[j], acc[i][j]);
        }
        __syncthreads();
    }
#pragma unroll
    for (int i = 0; i < 4; ++i)
#pragma unroll
        for (int j = 0; j < 4; ++j)
            atomicAdd(&g_hebb[(o0 + ty * 4 + i) * DIN + d0 + tx * 4 + j], acc[i][j]);
}

// ---------------- m2[o] += sum_b fast[b,o]^2 ---------------------------------
__global__ __launch_bounds__(256)
void m2_kernel()
{
    const int c = threadIdx.x;
    const int r0 = blockIdx.x * 256;
    float s0 = 0.f, s1 = 0.f;
    for (int r = r0; r < r0 + 256; ++r) {
        float f0 = g_fast[(size_t)r * DOUT + c];
        float f1 = g_fast[(size_t)r * DOUT + c + 256];
        s0 = fmaf(f0, f0, s0);
        s1 = fmaf(f1, f1, s1);
    }
    atomicAdd(&g_m2[c], s0);
    atomicAdd(&g_m2[c + 256], s1);
}

// ---------------- combine + swish-beta + layernorm ---------------------------
__global__ __launch_bounds__(128)
void finalize_kernel(const float* __restrict__ gamma,
                     const float* __restrict__ lbeta,
                     float* __restrict__ outp)
{
    const int b = blockIdx.x;
    const int tid = threadIdx.x;
    const float sens = g_gates[(size_t)b * 3 + 1];
    const float gate = g_gates[(size_t)b * 3 + 2];
    const float be = 0.5f + 2.0f * sens;

    float a[4];
    float s = 0.f, sq = 0.f;
#pragma unroll
    for (int i = 0; i < 4; ++i) {
        const int c = tid + i * 128;
        float cmb = g_slow[(size_t)b * DOUT + c] + g_fast[(size_t)b * DOUT + c] * gate;
        float act = cmb * sigf(be * cmb);
        a[i] = act;
        s += act;
        sq = fmaf(act, act, sq);
    }

    __shared__ float sh[8];
#pragma unroll
    for (int o = 16; o > 0; o >>= 1) {
        s  += __shfl_down_sync(0xffffffffu, s,  o);
        sq += __shfl_down_sync(0xffffffffu, sq, o);
    }
    const int lane = tid & 31, warp = tid >> 5;
    if (lane == 0) { sh[warp] = s; sh[4 + warp] = sq; }
    __syncthreads();
    if (tid == 0) {
        sh[0] = sh[0] + sh[1] + sh[2] + sh[3];
        sh[4] = sh[4] + sh[5] + sh[6] + sh[7];
    }
    __syncthreads();
    const float mu  = sh[0] * (1.0f / DOUT);
    const float var = sh[4] * (1.0f / DOUT) - mu * mu;
    const float inv = rsqrtf(var + 1e-5f);
#pragma unroll
    for (int i = 0; i < 4; ++i) {
        const int c = tid + i * 128;
        outp[(size_t)b * DOUT + c] = (a[i] - mu) * inv * gamma[c] + lbeta[c];
    }
}

// ---------------- W_fast update + stats output -------------------------------
__global__ void wfast_kernel(const float* __restrict__ Wf,
                             float* __restrict__ out_wf,
                             float* __restrict__ out_st)
{
    const int o = blockIdx.x;
    const float rate = g_stats[0] * (0.1f / (float)BATCH);
    const float m2 = g_m2[o] * (1.0f / (float)BATCH);
    for (int d = threadIdx.x; d < DIN; d += blockDim.x) {
        const float wf = Wf[o * DIN + d];
        const float hebb = g_hebb[o * DIN + d] * (1.0f / (float)BATCH);
        out_wf[o * DIN + d] = wf + tanhf(hebb - m2 * wf) * rate;
    }
    if (o == 0 && threadIdx.x < 3)
        out_st[threadIdx.x] = g_stats[threadIdx.x] * (1.0f / (float)BATCH);
}

// ---------------- launch -----------------------------------------------------
extern "C" void kernel_launch(void* const* d_in, const int* in_sizes, int n_in,
                              void* d_out, int out_size)
{
    (void)in_sizes; (void)n_in; (void)out_size;

    const float* x      = (const float*)d_in[0];
    const int*   step   = (const int*)  d_in[1];
    const float* cms_w1 = (const float*)d_in[2];
    const float* cms_b1 = (const float*)d_in[3];
    const float* cms_w2 = (const float*)d_in[4];
    const float* cms_b2 = (const float*)d_in[5];
    const float* gmw    = (const float*)d_in[6];
    const float* gmb    = (const float*)d_in[7];
    const float* gsw    = (const float*)d_in[8];
    const float* gsb    = (const float*)d_in[9];
    const float* ggw    = (const float*)d_in[10];
    const float* ggb    = (const float*)d_in[11];
    const float* gow    = (const float*)d_in[12];
    const float* gob    = (const float*)d_in[13];
    const float* Wslow  = (const float*)d_in[14];
    const float* Wfast  = (const float*)d_in[15];
    const float* gamma  = (const float*)d_in[16];
    const float* lbeta  = (const float*)d_in[17];

    float* out    = (float*)d_out;
    float* out_ln = out;
    float* out_wf = out + (size_t)BATCH * DOUT;
    float* out_st = out_wf + DOUT * DIN;

    void* p;
    cudaGetSymbolAddress(&p, g_buf);  float* buf   = (float*)p;
    cudaGetSymbolAddress(&p, g_h);    float* hbuf  = (float*)p;
    cudaGetSymbolAddress(&p, g_slow); float* slow  = (float*)p;
    cudaGetSymbolAddress(&p, g_fast); float* fastb = (float*)p;

    const dim3 blk(256);
    const dim3 gh(HIDN / 128, BATCH / 128);  // N=1024 GEMMs
    const dim3 gd(DIN  / 128, BATCH / 128);  // N=512  GEMMs

    zero_kernel<<<256, 256>>>();

    // CMS level 0 (freq 1: always active); residual source is x itself
    gemm_kernel<EPI_RELU ><<<gh, blk>>>(x,    cms_w1, cms_b1, nullptr, hbuf, HIDN, DIN,  step, 1);
    gemm_kernel<EPI_RESID><<<gd, blk>>>(hbuf, cms_w2, cms_b2, x,       buf,  DIN,  HIDN, step, 1);
    // CMS level 1 (freq 4)
    gemm_kernel<EPI_RELU ><<<gh, blk>>>(buf,  cms_w1 + HIDN * DIN,     cms_b1 + HIDN,     nullptr, hbuf, HIDN, DIN,  step, 4);
    gemm_kernel<EPI_RESID><<<gd, blk>>>(hbuf, cms_w2 + DIN * HIDN,     cms_b2 + DIN,      buf,     buf,  DIN,  HIDN, step, 4);
    // CMS level 2 (freq 16)
    gemm_kernel<EPI_RELU ><<<gh, blk>>>(buf,  cms_w1 + 2 * HIDN * DIN, cms_b1 + 2 * HIDN, nullptr, hbuf, HIDN, DIN,  step, 16);
    gemm_kernel<EPI_RESID><<<gd, blk>>>(hbuf, cms_w2 + 2 * DIN * HIDN, cms_b2 + 2 * DIN,  buf,     buf,  DIN,  HIDN, step, 16);

    // gate hidden sums (sigmoid(metab)+sigmoid(sens)+sigmoid(gate)) into hbuf
    gemm_kernel<EPI_SIGW><<<gh, blk>>>(buf, gmw, gmb, nullptr, hbuf, HIDN, DIN, step, 1);
    gemm_kernel<EPI_SIGA><<<gh, blk>>>(buf, gsw, gsb, nullptr, hbuf, HIDN, DIN, step, 1);
    gemm_kernel<EPI_SIGA><<<gh, blk>>>(buf, ggw, ggb, nullptr, hbuf, HIDN, DIN, step, 1);

    gateout_kernel<<<BATCH / 8, 256>>>(hbuf, gow, gob);

    // slow / fast projections
    gemm_kernel<EPI_NONE><<<gd, blk>>>(buf, Wslow, nullptr, nullptr, slow,  DOUT, DIN, step, 1);
    gemm_kernel<EPI_NONE><<<gd, blk>>>(buf, Wfast, nullptr, nullptr, fastb, DOUT, DIN, step, 1);

    hebb_kernel<<<dim3(8, 8, 128), 256>>>();
    m2_kernel<<<BATCH / 256, 256>>>();

    finalize_kernel<<<BATCH, 128>>>(gamma, lbeta, out_ln);
    wfast_kernel<<<DOUT, 256>>>(Wfast, out_wf, out_st);
}

// round 2
// speedup vs baseline: 2.6046x; 2.6046x over previous
#include <cuda_runtime.h>
#include <math.h>
#include <stdint.h>

#define BATCH 65536
#define DIN   512
#define DOUT  512
#define HIDN  1024

// ---------------- scratch (static device globals; no allocation) -------------
__device__ float g_buf [(size_t)BATCH * DIN];   // evolving x / x_cms
__device__ float g_h   [(size_t)BATCH * HIDN];  // cms hidden, then gate-sigmoid sum
__device__ float g_slow[(size_t)BATCH * DOUT];
__device__ float g_fast[(size_t)BATCH * DOUT];
__device__ float g_gates[(size_t)BATCH * 3];
__device__ float g_hebb[DOUT * DIN];            // split-K accumulator (sum over b)
__device__ float g_m2  [DOUT];                  // sum_b fast^2
__device__ float g_stats[4];                    // sums of metab/sens/gate

__device__ __forceinline__ float sigf(float x) { return 1.0f / (1.0f + expf(-x)); }

__device__ __forceinline__ uint32_t f2tf32(float x) {
    uint32_t r;
    asm("cvt.rna.tf32.f32 %0, %1;" : "=r"(r) : "f"(x));
    return r;
}

__device__ __forceinline__ void mma_tf32(float* c, const uint32_t* a, const uint32_t* b) {
    asm volatile(
        "mma.sync.aligned.m16n8k8.row.col.f32.tf32.tf32.f32 "
        "{%0,%1,%2,%3}, {%4,%5,%6,%7}, {%8,%9}, {%0,%1,%2,%3};\n"
        : "+f"(c[0]), "+f"(c[1]), "+f"(c[2]), "+f"(c[3])
        : "r"(a[0]), "r"(a[1]), "r"(a[2]), "r"(a[3]), "r"(b[0]), "r"(b[1]));
}

__device__ __forceinline__ void cp16(void* smem, const void* g) {
    uint32_t s = (uint32_t)__cvta_generic_to_shared(smem);
    asm volatile("cp.async.cg.shared.global [%0], [%1], 16;\n" :: "r"(s), "l"(g));
}
__device__ __forceinline__ void cp_commit() { asm volatile("cp.async.commit_group;\n"); }
template <int N>
__device__ __forceinline__ void cp_wait() { asm volatile("cp.async.wait_group %0;\n" :: "n"(N)); }

// ---------------- zero accumulators ------------------------------------------
__global__ void zero_kernel() {
    int idx = blockIdx.x * blockDim.x + threadIdx.x;
    int stride = gridDim.x * blockDim.x;
    for (int i = idx; i < DOUT * DIN; i += stride) g_hebb[i] = 0.0f;
    if (idx < DOUT) g_m2[idx] = 0.0f;
    if (idx < 4)    g_stats[idx] = 0.0f;
}

// ---------------- tf32 tensor-core GEMM: C[m,n] = epi(A[m,:].W[n,:] + b[n]) --
enum { EPI_RELU = 0, EPI_RESID = 1, EPI_SIGW = 2, EPI_SIGA = 3, EPI_NONE = 4 };

#define SPITCH 20   // 16 k-floats + 4 pad -> conflict-free frag loads

template <int EPI>
__global__ __launch_bounds__(256)
void mma_gemm(const float* __restrict__ A, const float* __restrict__ W,
              const float* __restrict__ bias, const float* __restrict__ R,
              float* __restrict__ C, int N, int K,
              const int* __restrict__ step, int freq)
{
    if (freq > 1) { if ((step[0] % freq) != 0) return; }

    __shared__ float As[2][128][SPITCH];
    __shared__ float Bs[2][128][SPITCH];

    const int tid  = threadIdx.x;
    const int lane = tid & 31;
    const int warp = tid >> 5;
    const int wm   = warp & 3;   // 4 warps over M -> 32 rows each
    const int wn   = warp >> 2;  // 2 warps over N -> 64 cols each
    const int m0   = blockIdx.y * 128;
    const int n0   = blockIdx.x * 128;

    float acc[2][8][4];
#pragma unroll
    for (int mt = 0; mt < 2; ++mt)
#pragma unroll
        for (int nt = 0; nt < 8; ++nt)
#pragma unroll
            for (int i = 0; i < 4; ++i) acc[mt][nt][i] = 0.0f;

    const int lr = tid >> 2;   // 0..63
    const int lc = tid & 3;    // k-chunk (float4)

    const float* Ag = A + (size_t)(m0 + lr) * K + lc * 4;
    const float* Wg = W + (size_t)(n0 + lr) * K + lc * 4;

    const int KT = K >> 4;

    // prefetch tile 0
    {
        cp16(&As[0][lr][lc * 4],      Ag);
        cp16(&As[0][lr + 64][lc * 4], Ag + (size_t)64 * K);
        cp16(&Bs[0][lr][lc * 4],      Wg);
        cp16(&Bs[0][lr + 64][lc * 4], Wg + (size_t)64 * K);
        cp_commit();
    }

    for (int kt = 0; kt < KT; ++kt) {
        const int cur = kt & 1;
        if (kt + 1 < KT) {
            const int nxt = cur ^ 1;
            const size_t ko = (size_t)(kt + 1) * 16;
            cp16(&As[nxt][lr][lc * 4],      Ag + ko);
            cp16(&As[nxt][lr + 64][lc * 4], Ag + (size_t)64 * K + ko);
            cp16(&Bs[nxt][lr][lc * 4],      Wg + ko);
            cp16(&Bs[nxt][lr + 64][lc * 4], Wg + (size_t)64 * K + ko);
            cp_commit();
            cp_wait<1>();
        } else {
            cp_wait<0>();
        }
        __syncthreads();

#pragma unroll
        for (int ks = 0; ks < 2; ++ks) {
            const int kk = ks * 8 + (lane & 3);
            uint32_t af[2][4];
#pragma unroll
            for (int mt = 0; mt < 2; ++mt) {
                const int mr = wm * 32 + mt * 16 + (lane >> 2);
                af[mt][0] = f2tf32(As[cur][mr][kk]);
                af[mt][1] = f2tf32(As[cur][mr + 8][kk]);
                af[mt][2] = f2tf32(As[cur][mr][kk + 4]);
                af[mt][3] = f2tf32(As[cur][mr + 8][kk + 4]);
            }
            uint32_t bf[8][2];
#pragma unroll
            for (int nt = 0; nt < 8; ++nt) {
                const int nc = wn * 64 + nt * 8 + (lane >> 2);
                bf[nt][0] = f2tf32(Bs[cur][nc][kk]);
                bf[nt][1] = f2tf32(Bs[cur][nc][kk + 4]);
            }
#pragma unroll
            for (int mt = 0; mt < 2; ++mt)
#pragma unroll
                for (int nt = 0; nt < 8; ++nt)
                    mma_tf32(acc[mt][nt], af[mt], bf[nt]);
        }
        __syncthreads();
    }

    // epilogue
#pragma unroll
    for (int mt = 0; mt < 2; ++mt) {
#pragma unroll
        for (int nt = 0; nt < 8; ++nt) {
            const int col = n0 + wn * 64 + nt * 8 + (lane & 3) * 2;
            float bv0 = 0.f, bv1 = 0.f;
            if (EPI != EPI_NONE) { bv0 = bias[col]; bv1 = bias[col + 1]; }
#pragma unroll
            for (int h = 0; h < 2; ++h) {
                const int row = m0 + wm * 32 + mt * 16 + (lane >> 2) + h * 8;
                const size_t idx = (size_t)row * N + col;
                float v0 = acc[mt][nt][h * 2 + 0] + bv0;
                float v1 = acc[mt][nt][h * 2 + 1] + bv1;
                if (EPI == EPI_RELU) {
                    v0 = v0 > 0.f ? v0 : 0.f;
                    v1 = v1 > 0.f ? v1 : 0.f;
                } else if (EPI == EPI_RESID) {
                    v0 += R[idx]; v1 += R[idx + 1];
                } else if (EPI == EPI_SIGW) {
                    v0 = sigf(v0); v1 = sigf(v1);
                } else if (EPI == EPI_SIGA) {
                    v0 = C[idx] + sigf(v0); v1 = C[idx + 1] + sigf(v1);
                }
                *(float2*)&C[idx] = make_float2(v0, v1);
            }
        }
    }
}

// ---------------- hebb: g_hebb[o,d] += sum_b fast[b,o] * x_cms[b,d] ----------
// tf32 split-K GEMM: M=512(o), N=512(d), K=65536 split into 32 chunks of 2048.
#define HPITCH 136  // 128 + 8 pad -> conflict-free

__global__ __launch_bounds__(256)
void hebb_mma_kernel()
{
    __shared__ float Fs[2][16][HPITCH];
    __shared__ float Xs[2][16][HPITCH];

    const int tid  = threadIdx.x;
    const int lane = tid & 31;
    const int warp = tid >> 5;
    const int wm   = warp & 3;
    const int wn   = warp >> 2;
    const int o0   = blockIdx.x * 128;
    const int d0   = blockIdx.y * 128;
    const int b0   = blockIdx.z * 2048;

    float acc[2][8][4];
#pragma unroll
    for (int mt = 0; mt < 2; ++mt)
#pragma unroll
        for (int nt = 0; nt < 8; ++nt)
#pragma unroll
            for (int i = 0; i < 4; ++i) acc[mt][nt][i] = 0.0f;

    // loader: 16 rows (b) x 32 float4 (128 floats) per operand, 2 chunks/thread
    const int id0 = tid;          // 0..255
    const int id1 = tid + 256;    // 256..511
    const int r0 = id0 >> 5, c0 = id0 & 31;
    const int r1 = id1 >> 5, c1 = id1 & 31;

    // prefetch tile 0
    {
        const int bb = b0;
        cp16(&Fs[0][r0][c0 * 4], &g_fast[(size_t)(bb + r0) * DOUT + o0 + c0 * 4]);
        cp16(&Fs[0][r1][c1 * 4], &g_fast[(size_t)(bb + r1) * DOUT + o0 + c1 * 4]);
        cp16(&Xs[0][r0][c0 * 4], &g_buf [(size_t)(bb + r0) * DIN  + d0 + c0 * 4]);
        cp16(&Xs[0][r1][c1 * 4], &g_buf [(size_t)(bb + r1) * DIN  + d0 + c1 * 4]);
        cp_commit();
    }

    const int KT = 2048 / 16;
    for (int kt = 0; kt < KT; ++kt) {
        const int cur = kt & 1;
        if (kt + 1 < KT) {
            const int nxt = cur ^ 1;
            const int bb = b0 + (kt + 1) * 16;
            cp16(&Fs[nxt][r0][c0 * 4], &g_fast[(size_t)(bb + r0) * DOUT + o0 + c0 * 4]);
            cp16(&Fs[nxt][r1][c1 * 4], &g_fast[(size_t)(bb + r1) * DOUT + o0 + c1 * 4]);
            cp16(&Xs[nxt][r0][c0 * 4], &g_buf [(size_t)(bb + r0) * DIN  + d0 + c0 * 4]);
            cp16(&Xs[nxt][r1][c1 * 4], &g_buf [(size_t)(bb + r1) * DIN  + d0 + c1 * 4]);
            cp_commit();
            cp_wait<1>();
        } else {
            cp_wait<0>();
        }
        __syncthreads();

#pragma unroll
        for (int ks = 0; ks < 2; ++ks) {
            const int kk = ks * 8 + (lane & 3);
            uint32_t af[2][4];
#pragma unroll
            for (int mt = 0; mt < 2; ++mt) {
                const int mr = wm * 32 + mt * 16 + (lane >> 2);
                af[mt][0] = f2tf32(Fs[cur][kk][mr]);
                af[mt][1] = f2tf32(Fs[cur][kk][mr + 8]);
                af[mt][2] = f2tf32(Fs[cur][kk + 4][mr]);
                af[mt][3] = f2tf32(Fs[cur][kk + 4][mr + 8]);
            }
            uint32_t bf[8][2];
#pragma unroll
            for (int nt = 0; nt < 8; ++nt) {
                const int nc = wn * 64 + nt * 8 + (lane >> 2);
                bf[nt][0] = f2tf32(Xs[cur][kk][nc]);
                bf[nt][1] = f2tf32(Xs[cur][kk + 4][nc]);
            }
#pragma unroll
            for (int mt = 0; mt < 2; ++mt)
#pragma unroll
                for (int nt = 0; nt < 8; ++nt)
                    mma_tf32(acc[mt][nt], af[mt], bf[nt]);
        }
        __syncthreads();
    }

#pragma unroll
    for (int mt = 0; mt < 2; ++mt)
#pragma unroll
        for (int nt = 0; nt < 8; ++nt) {
            const int col = d0 + wn * 64 + nt * 8 + (lane & 3) * 2;
#pragma unroll
            for (int h = 0; h < 2; ++h) {
                const int row = o0 + wm * 32 + mt * 16 + (lane >> 2) + h * 8;
                atomicAdd(&g_hebb[row * DIN + col],     acc[mt][nt][h * 2 + 0]);
                atomicAdd(&g_hebb[row * DIN + col + 1], acc[mt][nt][h * 2 + 1]);
            }
        }
}

// ---------------- gates head: B x 1024 -> B x 3 (+ stats sums) ---------------
__global__ __launch_bounds__(256)
void gateout_kernel(const float* __restrict__ gsum,
                    const float* __restrict__ w,   // [3][1024]
                    const float* __restrict__ b3)  // [3]
{
    __shared__ float sw[3 * HIDN];
    __shared__ float sacc[3];
    const int tid = threadIdx.x;
    for (int i = tid; i < 3 * HIDN; i += 256) sw[i] = w[i];
    if (tid < 3) sacc[tid] = 0.0f;
    __syncthreads();

    const int lane = tid & 31, warp = tid >> 5;
    const int b = blockIdx.x * 8 + warp;
    const float* row = gsum + (size_t)b * HIDN;
    float a0 = 0.f, a1 = 0.f, a2 = 0.f;
    for (int h = lane; h < HIDN; h += 32) {
        float v = row[h];
        a0 = fmaf(v, sw[h],            a0);
        a1 = fmaf(v, sw[HIDN + h],     a1);
        a2 = fmaf(v, sw[2 * HIDN + h], a2);
    }
#pragma unroll
    for (int o = 16; o > 0; o >>= 1) {
        a0 += __shfl_down_sync(0xffffffffu, a0, o);
        a1 += __shfl_down_sync(0xffffffffu, a1, o);
        a2 += __shfl_down_sync(0xffffffffu, a2, o);
    }
    if (lane == 0) {
        float s0 = sigf(a0 + b3[0]);
        float s1 = sigf(a1 + b3[1]);
        float s2 = sigf(a2 + b3[2]);
        g_gates[(size_t)b * 3 + 0] = s0;
        g_gates[(size_t)b * 3 + 1] = s1;
        g_gates[(size_t)b * 3 + 2] = s2;
        atomicAdd(&sacc[0], s0);
        atomicAdd(&sacc[1], s1);
        atomicAdd(&sacc[2], s2);
    }
    __syncthreads();
    if (tid < 3) atomicAdd(&g_stats[tid], sacc[tid]);
}

// ---------------- m2[o] += sum_b fast[b,o]^2 ---------------------------------
__global__ __launch_bounds__(256)
void m2_kernel()
{
    const int c = threadIdx.x;
    const int r0 = blockIdx.x * 256;
    float s0 = 0.f, s1 = 0.f;
    for (int r = r0; r < r0 + 256; ++r) {
        float f0 = g_fast[(size_t)r * DOUT + c];
        float f1 = g_fast[(size_t)r * DOUT + c + 256];
        s0 = fmaf(f0, f0, s0);
        s1 = fmaf(f1, f1, s1);
    }
    atomicAdd(&g_m2[c], s0);
    atomicAdd(&g_m2[c + 256], s1);
}

// ---------------- combine + swish-beta + layernorm ---------------------------
__global__ __launch_bounds__(128)
void finalize_kernel(const float* __restrict__ gamma,
                     const float* __restrict__ lbeta,
                     float* __restrict__ outp)
{
    const int b = blockIdx.x;
    const int tid = threadIdx.x;
    const float sens = g_gates[(size_t)b * 3 + 1];
    const float gate = g_gates[(size_t)b * 3 + 2];
    const float be = 0.5f + 2.0f * sens;

    float a[4];
    float s = 0.f, sq = 0.f;
#pragma unroll
    for (int i = 0; i < 4; ++i) {
        const int c = tid + i * 128;
        float cmb = g_slow[(size_t)b * DOUT + c] + g_fast[(size_t)b * DOUT + c] * gate;
        float act = cmb * sigf(be * cmb);
        a[i] = act;
        s += act;
        sq = fmaf(act, act, sq);
    }

    __shared__ float sh[8];
#pragma unroll
    for (int o = 16; o > 0; o >>= 1) {
        s  += __shfl_down_sync(0xffffffffu, s,  o);
        sq += __shfl_down_sync(0xffffffffu, sq, o);
    }
    const int lane = tid & 31, warp = tid >> 5;
    if (lane == 0) { sh[warp] = s; sh[4 + warp] = sq; }
    __syncthreads();
    if (tid == 0) {
        sh[0] = sh[0] + sh[1] + sh[2] + sh[3];
        sh[4] = sh[4] + sh[5] + sh[6] + sh[7];
    }
    __syncthreads();
    const float mu  = sh[0] * (1.0f / DOUT);
    const float var = sh[4] * (1.0f / DOUT) - mu * mu;
    const float inv = rsqrtf(var + 1e-5f);
#pragma unroll
    for (int i = 0; i < 4; ++i) {
        const int c = tid + i * 128;
        outp[(size_t)b * DOUT + c] = (a[i] - mu) * inv * gamma[c] + lbeta[c];
    }
}

// ---------------- W_fast update + stats output -------------------------------
__global__ void wfast_kernel(const float* __restrict__ Wf,
                             float* __restrict__ out_wf,
                             float* __restrict__ out_st)
{
    const int o = blockIdx.x;
    const float rate = g_stats[0] * (0.1f / (float)BATCH);
    const float m2 = g_m2[o] * (1.0f / (float)BATCH);
    for (int d = threadIdx.x; d < DIN; d += blockDim.x) {
        const float wf = Wf[o * DIN + d];
        const float hebb = g_hebb[o * DIN + d] * (1.0f / (float)BATCH);
        out_wf[o * DIN + d] = wf + tanhf(hebb - m2 * wf) * rate;
    }
    if (o == 0 && threadIdx.x < 3)
        out_st[threadIdx.x] = g_stats[threadIdx.x] * (1.0f / (float)BATCH);
}

// ---------------- launch -----------------------------------------------------
extern "C" void kernel_launch(void* const* d_in, const int* in_sizes, int n_in,
                              void* d_out, int out_size)
{
    (void)in_sizes; (void)n_in; (void)out_size;

    const float* x      = (const float*)d_in[0];
    const int*   step   = (const int*)  d_in[1];
    const float* cms_w1 = (const float*)d_in[2];
    const float* cms_b1 = (const float*)d_in[3];
    const float* cms_w2 = (const float*)d_in[4];
    const float* cms_b2 = (const float*)d_in[5];
    const float* gmw    = (const float*)d_in[6];
    const float* gmb    = (const float*)d_in[7];
    const float* gsw    = (const float*)d_in[8];
    const float* gsb    = (const float*)d_in[9];
    const float* ggw    = (const float*)d_in[10];
    const float* ggb    = (const float*)d_in[11];
    const float* gow    = (const float*)d_in[12];
    const float* gob    = (const float*)d_in[13];
    const float* Wslow  = (const float*)d_in[14];
    const float* Wfast  = (const float*)d_in[15];
    const float* gamma  = (const float*)d_in[16];
    const float* lbeta  = (const float*)d_in[17];

    float* out    = (float*)d_out;
    float* out_ln = out;
    float* out_wf = out + (size_t)BATCH * DOUT;
    float* out_st = out_wf + DOUT * DIN;

    void* p;
    cudaGetSymbolAddress(&p, g_buf);  float* buf   = (float*)p;
    cudaGetSymbolAddress(&p, g_h);    float* hbuf  = (float*)p;
    cudaGetSymbolAddress(&p, g_slow); float* slow  = (float*)p;
    cudaGetSymbolAddress(&p, g_fast); float* fastb = (float*)p;

    const dim3 blk(256);
    const dim3 gh(HIDN / 128, BATCH / 128);  // N=1024 GEMMs
    const dim3 gd(DIN  / 128, BATCH / 128);  // N=512  GEMMs

    zero_kernel<<<256, 256>>>();

    // CMS level 0 (freq 1: always active); residual source is x itself
    mma_gemm<EPI_RELU ><<<gh, blk>>>(x,    cms_w1, cms_b1, nullptr, hbuf, HIDN, DIN,  step, 1);
    mma_gemm<EPI_RESID><<<gd, blk>>>(hbuf, cms_w2, cms_b2, x,       buf,  DIN,  HIDN, step, 1);
    // CMS level 1 (freq 4)
    mma_gemm<EPI_RELU ><<<gh, blk>>>(buf,  cms_w1 + HIDN * DIN,     cms_b1 + HIDN,     nullptr, hbuf, HIDN, DIN,  step, 4);
    mma_gemm<EPI_RESID><<<gd, blk>>>(hbuf, cms_w2 + DIN * HIDN,     cms_b2 + DIN,      buf,     buf,  DIN,  HIDN, step, 4);
    // CMS level 2 (freq 16)
    mma_gemm<EPI_RELU ><<<gh, blk>>>(buf,  cms_w1 + 2 * HIDN * DIN, cms_b1 + 2 * HIDN, nullptr, hbuf, HIDN, DIN,  step, 16);
    mma_gemm<EPI_RESID><<<gd, blk>>>(hbuf, cms_w2 + 2 * DIN * HIDN, cms_b2 + 2 * DIN,  buf,     buf,  DIN,  HIDN, step, 16);

    // gate hidden sums (sigmoid(metab)+sigmoid(sens)+sigmoid(gate)) into hbuf
    mma_gemm<EPI_SIGW><<<gh, blk>>>(buf, gmw, gmb, nullptr, hbuf, HIDN, DIN, step, 1);
    mma_gemm<EPI_SIGA><<<gh, blk>>>(buf, gsw, gsb, nullptr, hbuf, HIDN, DIN, step, 1);
    mma_gemm<EPI_SIGA><<<gh, blk>>>(buf, ggw, ggb, nullptr, hbuf, HIDN, DIN, step, 1);

    gateout_kernel<<<BATCH / 8, 256>>>(hbuf, gow, gob);

    // slow / fast projections
    mma_gemm<EPI_NONE><<<gd, blk>>>(buf, Wslow, nullptr, nullptr, slow,  DOUT, DIN, step, 1);
    mma_gemm<EPI_NONE><<<gd, blk>>>(buf, Wfast, nullptr, nullptr, fastb, DOUT, DIN, step, 1);

    hebb_mma_kernel<<<dim3(4, 4, 32), blk>>>();
    m2_kernel<<<BATCH / 256, 256>>>();

    finalize_kernel<<<BATCH, 128>>>(gamma, lbeta, out_ln);
    wfast_kernel<<<DOUT, 256>>>(Wfast, out_wf, out_st);
}

// round 4
// speedup vs baseline: 2.9021x; 1.1142x over previous
#include <cuda_runtime.h>
#include <math.h>
#include <stdint.h>

#define BATCH 65536
#define DIN   512
#define DOUT  512
#define HIDN  1024

// ---------------- scratch (static device globals; no allocation) -------------
__device__ float g_buf [(size_t)BATCH * DIN];   // evolving x / x_cms (tf32-rounded)
__device__ float g_h   [(size_t)BATCH * HIDN];  // cms hidden / gate-sigmoid sum
__device__ float g_slow[(size_t)BATCH * DOUT];
__device__ float g_fast[(size_t)BATCH * DOUT];
__device__ float g_gates[(size_t)BATCH * 3];
__device__ float g_hebb[DOUT * DIN];
__device__ float g_m2  [DOUT];
__device__ float g_stats[4];

// tf32-rounded weight copies
__device__ float g_w1r[3 * HIDN * DIN];
__device__ float g_w2r[3 * DIN * HIDN];
__device__ float g_gwr[3 * HIDN * DIN];   // metab, sens, gate stacked
__device__ float g_sfr[2 * DOUT * DIN];   // slow, fast stacked

__device__ __forceinline__ float sigf(float x) { return 1.0f / (1.0f + expf(-x)); }

__device__ __forceinline__ uint32_t f2tf32(float x) {
    uint32_t r;
    asm("cvt.rna.tf32.f32 %0, %1;" : "=r"(r) : "f"(x));
    return r;
}
__device__ __forceinline__ float roundtf(float x) { return __uint_as_float(f2tf32(x)); }

__device__ __forceinline__ void mma_tf32(float* c, const uint32_t* a, const uint32_t* b) {
    asm volatile(
        "mma.sync.aligned.m16n8k8.row.col.f32.tf32.tf32.f32 "
        "{%0,%1,%2,%3}, {%4,%5,%6,%7}, {%8,%9}, {%0,%1,%2,%3};\n"
        : "+f"(c[0]), "+f"(c[1]), "+f"(c[2]), "+f"(c[3])
        : "r"(a[0]), "r"(a[1]), "r"(a[2]), "r"(a[3]), "r"(b[0]), "r"(b[1]));
}

__device__ __forceinline__ void cp16(void* smem, const void* g) {
    uint32_t s = (uint32_t)__cvta_generic_to_shared(smem);
    asm volatile("cp.async.cg.shared.global [%0], [%1], 16;\n" :: "r"(s), "l"(g));
}
__device__ __forceinline__ void cp_commit() { asm volatile("cp.async.commit_group;\n"); }
template <int N>
__device__ __forceinline__ void cp_wait() { asm volatile("cp.async.wait_group %0;\n" :: "n"(N)); }

// ---------------- prepass: zero accumulators + round weights -----------------
#define NW1 (3 * HIDN * DIN)
#define NW2 (3 * DIN * HIDN)
#define NGW (HIDN * DIN)
#define NSF (DOUT * DIN)

__global__ void prep_kernel(const float* __restrict__ w1, const float* __restrict__ w2,
                            const float* __restrict__ gm, const float* __restrict__ gs,
                            const float* __restrict__ gg, const float* __restrict__ ws,
                            const float* __restrict__ wf)
{
    const int idx = blockIdx.x * blockDim.x + threadIdx.x;
    const int stride = gridDim.x * blockDim.x;
    for (int i = idx; i < NW1; i += stride) g_w1r[i] = roundtf(w1[i]);
    for (int i = idx; i < NW2; i += stride) g_w2r[i] = roundtf(w2[i]);
    for (int i = idx; i < NGW; i += stride) {
        g_gwr[i]           = roundtf(gm[i]);
        g_gwr[i + NGW]     = roundtf(gs[i]);
        g_gwr[i + 2 * NGW] = roundtf(gg[i]);
    }
    for (int i = idx; i < NSF; i += stride) {
        g_sfr[i]       = roundtf(ws[i]);
        g_sfr[i + NSF] = roundtf(wf[i]);
    }
    for (int i = idx; i < DOUT * DIN; i += stride) g_hebb[i] = 0.0f;
    if (idx < DOUT) g_m2[idx] = 0.0f;
    if (idx < 4)    g_stats[idx] = 0.0f;
}

// ---------------- tf32 tensor-core GEMM --------------------------------------
enum { EPI_RELU = 0, EPI_RESID = 1, EPI_SIGW = 2, EPI_SIGA = 3, EPI_NONE = 4 };

#define SPITCH 20   // 16 k-floats + 4 pad -> conflict-free frag loads

// block tile 128x128x16; 8 warps as 2(M) x 4(N); warp tile 64x32.
template <int EPI, bool CVTA, bool ROUND_OUT>
__global__ __launch_bounds__(256, 2)
void mma_gemm(const float* __restrict__ A, const float* __restrict__ W,
              const float* __restrict__ bias, const float* __restrict__ R,
              float* __restrict__ C, int N, int K,
              const int* __restrict__ step, int freq)
{
    if (freq > 1) { if ((step[0] % freq) != 0) return; }

    __shared__ float As[2][128][SPITCH];
    __shared__ float Bs[2][128][SPITCH];

    const int tid  = threadIdx.x;
    const int lane = tid & 31;
    const int warp = tid >> 5;
    const int wm   = warp >> 2;  // 0..1 -> 64 rows
    const int wn   = warp & 3;   // 0..3 -> 32 cols
    const int m0   = blockIdx.y * 128;
    const int n0   = blockIdx.x * 128;

    float acc[4][4][4];
#pragma unroll
    for (int mt = 0; mt < 4; ++mt)
#pragma unroll
        for (int nt = 0; nt < 4; ++nt)
#pragma unroll
            for (int i = 0; i < 4; ++i) acc[mt][nt][i] = 0.0f;

    const int lr = tid >> 2;   // 0..63
    const int lc = tid & 3;    // k-chunk (float4)

    const float* Ag = A + (size_t)(m0 + lr) * K + lc * 4;
    const float* Wg = W + (size_t)(n0 + lr) * K + lc * 4;

    const int KT = K >> 4;

    cp16(&As[0][lr][lc * 4],      Ag);
    cp16(&As[0][lr + 64][lc * 4], Ag + (size_t)64 * K);
    cp16(&Bs[0][lr][lc * 4],      Wg);
    cp16(&Bs[0][lr + 64][lc * 4], Wg + (size_t)64 * K);
    cp_commit();

    for (int kt = 0; kt < KT; ++kt) {
        const int cur = kt & 1;
        if (kt + 1 < KT) {
            const int nxt = cur ^ 1;
            const size_t ko = (size_t)(kt + 1) * 16;
            cp16(&As[nxt][lr][lc * 4],      Ag + ko);
            cp16(&As[nxt][lr + 64][lc * 4], Ag + (size_t)64 * K + ko);
            cp16(&Bs[nxt][lr][lc * 4],      Wg + ko);
            cp16(&Bs[nxt][lr + 64][lc * 4], Wg + (size_t)64 * K + ko);
            cp_commit();
            cp_wait<1>();
        } else {
            cp_wait<0>();
        }
        __syncthreads();

#pragma unroll
        for (int ks = 0; ks < 2; ++ks) {
            const int kk = ks * 8 + (lane & 3);
            uint32_t af[4][4];
#pragma unroll
            for (int mt = 0; mt < 4; ++mt) {
                const int mr = wm * 64 + mt * 16 + (lane >> 2);
                if (CVTA) {
                    af[mt][0] = f2tf32(As[cur][mr][kk]);
                    af[mt][1] = f2tf32(As[cur][mr + 8][kk]);
                    af[mt][2] = f2tf32(As[cur][mr][kk + 4]);
                    af[mt][3] = f2tf32(As[cur][mr + 8][kk + 4]);
                } else {
                    af[mt][0] = __float_as_uint(As[cur][mr][kk]);
                    af[mt][1] = __float_as_uint(As[cur][mr + 8][kk]);
                    af[mt][2] = __float_as_uint(As[cur][mr][kk + 4]);
                    af[mt][3] = __float_as_uint(As[cur][mr + 8][kk + 4]);
                }
            }
            uint32_t bf[4][2];
#pragma unroll
            for (int nt = 0; nt < 4; ++nt) {
                const int nc = wn * 32 + nt * 8 + (lane >> 2);
                bf[nt][0] = __float_as_uint(Bs[cur][nc][kk]);
                bf[nt][1] = __float_as_uint(Bs[cur][nc][kk + 4]);
            }
#pragma unroll
            for (int mt = 0; mt < 4; ++mt)
#pragma unroll
                for (int nt = 0; nt < 4; ++nt)
                    mma_tf32(acc[mt][nt], af[mt], bf[nt]);
        }
        __syncthreads();
    }

    // epilogue
#pragma unroll
    for (int mt = 0; mt < 4; ++mt) {
#pragma unroll
        for (int nt = 0; nt < 4; ++nt) {
            const int col = n0 + wn * 32 + nt * 8 + (lane & 3) * 2;
            float bv0 = 0.f, bv1 = 0.f;
            if (EPI != EPI_NONE) { bv0 = bias[col]; bv1 = bias[col + 1]; }
#pragma unroll
            for (int h = 0; h < 2; ++h) {
                const int row = m0 + wm * 64 + mt * 16 + (lane >> 2) + h * 8;
                const size_t idx = (size_t)row * N + col;
                float v0 = acc[mt][nt][h * 2 + 0] + bv0;
                float v1 = acc[mt][nt][h * 2 + 1] + bv1;
                if (EPI == EPI_RELU) {
                    v0 = v0 > 0.f ? v0 : 0.f;
                    v1 = v1 > 0.f ? v1 : 0.f;
                } else if (EPI == EPI_RESID) {
                    v0 += R[idx]; v1 += R[idx + 1];
                } else if (EPI == EPI_SIGW) {
                    v0 = sigf(v0); v1 = sigf(v1);
                } else if (EPI == EPI_SIGA) {
                    v0 = C[idx] + sigf(v0); v1 = C[idx + 1] + sigf(v1);
                }
                if (ROUND_OUT) { v0 = roundtf(v0); v1 = roundtf(v1); }
                *(float2*)&C[idx] = make_float2(v0, v1);
            }
        }
    }
}

// ---------------- hebb: g_hebb[o,d] += sum_b fast[b,o] * x_cms[b,d] ----------
#define HPITCH 136

__global__ __launch_bounds__(256, 2)
void hebb_mma_kernel()
{
    __shared__ float Fs[2][16][HPITCH];
    __shared__ float Xs[2][16][HPITCH];

    const int tid  = threadIdx.x;
    const int lane = tid & 31;
    const int warp = tid >> 5;
    const int wm   = warp >> 2;  // 0..1
    const int wn   = warp & 3;   // 0..3
    const int o0   = blockIdx.x * 128;
    const int d0   = blockIdx.y * 128;
    const int b0   = blockIdx.z * 2048;

    float acc[4][4][4];
#pragma unroll
    for (int mt = 0; mt < 4; ++mt)
#pragma unroll
        for (int nt = 0; nt < 4; ++nt)
#pragma unroll
            for (int i = 0; i < 4; ++i) acc[mt][nt][i] = 0.0f;

    const int r0 = tid >> 5,         c0 = tid & 31;
    const int r1 = (tid + 256) >> 5, c1 = tid & 31;

    {
        const int bb = b0;
        cp16(&Fs[0][r0][c0 * 4], &g_fast[(size_t)(bb + r0) * DOUT + o0 + c0 * 4]);
        cp16(&Fs[0][r1][c1 * 4], &g_fast[(size_t)(bb + r1) * DOUT + o0 + c1 * 4]);
        cp16(&Xs[0][r0][c0 * 4], &g_buf [(size_t)(bb + r0) * DIN  + d0 + c0 * 4]);
        cp16(&Xs[0][r1][c1 * 4], &g_buf [(size_t)(bb + r1) * DIN  + d0 + c1 * 4]);
        cp_commit();
    }

    const int KT = 2048 / 16;
    for (int kt = 0; kt < KT; ++kt) {
        const int cur = kt & 1;
        if (kt + 1 < KT) {
            const int nxt = cur ^ 1;
            const int bb = b0 + (kt + 1) * 16;
            cp16(&Fs[nxt][r0][c0 * 4], &g_fast[(size_t)(bb + r0) * DOUT + o0 + c0 * 4]);
            cp16(&Fs[nxt][r1][c1 * 4], &g_fast[(size_t)(bb + r1) * DOUT + o0 + c1 * 4]);
            cp16(&Xs[nxt][r0][c0 * 4], &g_buf [(size_t)(bb + r0) * DIN  + d0 + c0 * 4]);
            cp16(&Xs[nxt][r1][c1 * 4], &g_buf [(size_t)(bb + r1) * DIN  + d0 + c1 * 4]);
            cp_commit();
            cp_wait<1>();
        } else {
            cp_wait<0>();
        }
        __syncthreads();

#pragma unroll
        for (int ks = 0; ks < 2; ++ks) {
            const int kk = ks * 8 + (lane & 3);
            uint32_t af[4][4];
#pragma unroll
            for (int mt = 0; mt < 4; ++mt) {
                const int mr = wm * 64 + mt * 16 + (lane >> 2);
                af[mt][0] = f2tf32(Fs[cur][kk][mr]);       // g_fast: full fp32, cvt here
                af[mt][1] = f2tf32(Fs[cur][kk][mr + 8]);
                af[mt][2] = f2tf32(Fs[cur][kk + 4][mr]);
                af[mt][3] = f2tf32(Fs[cur][kk + 4][mr + 8]);
            }
            uint32_t bf[4][2];
#pragma unroll
            for (int nt = 0; nt < 4; ++nt) {
                const int nc = wn * 32 + nt * 8 + (lane >> 2);
                bf[nt][0] = __float_as_uint(Xs[cur][kk][nc]);      // g_buf pre-rounded
                bf[nt][1] = __float_as_uint(Xs[cur][kk + 4][nc]);
            }
#pragma unroll
            for (int mt = 0; mt < 4; ++mt)
#pragma unroll
                for (int nt = 0; nt < 4; ++nt)
                    mma_tf32(acc[mt][nt], af[mt], bf[nt]);
        }
        __syncthreads();
    }

#pragma unroll
    for (int mt = 0; mt < 4; ++mt)
#pragma unroll
        for (int nt = 0; nt < 4; ++nt) {
            const int col = d0 + wn * 32 + nt * 8 + (lane & 3) * 2;
#pragma unroll
            for (int h = 0; h < 2; ++h) {
                const int row = o0 + wm * 64 + mt * 16 + (lane >> 2) + h * 8;
                atomicAdd(&g_hebb[row * DIN + col],     acc[mt][nt][h * 2 + 0]);
                atomicAdd(&g_hebb[row * DIN + col + 1], acc[mt][nt][h * 2 + 1]);
            }
        }
}

// ---------------- gates head: B x 1024 -> B x 3 (+ stats sums) ---------------
__global__ __launch_bounds__(256)
void gateout_kernel(const float* __restrict__ gsum,
                    const float* __restrict__ w,
                    const float* __restrict__ b3)
{
    __shared__ float sw[3 * HIDN];
    __shared__ float sacc[3];
    const int tid = threadIdx.x;
    for (int i = tid; i < 3 * HIDN; i += 256) sw[i] = w[i];
    if (tid < 3) sacc[tid] = 0.0f;
    __syncthreads();

    const int lane = tid & 31, warp = tid >> 5;
    const int b = blockIdx.x * 8 + warp;
    const float* row = gsum + (size_t)b * HIDN;
    float a0 = 0.f, a1 = 0.f, a2 = 0.f;
    for (int h = lane; h < HIDN; h += 32) {
        float v = row[h];
        a0 = fmaf(v, sw[h],            a0);
        a1 = fmaf(v, sw[HIDN + h],     a1);
        a2 = fmaf(v, sw[2 * HIDN + h], a2);
    }
#pragma unroll
    for (int o = 16; o > 0; o >>= 1) {
        a0 += __shfl_down_sync(0xffffffffu, a0, o);
        a1 += __shfl_down_sync(0xffffffffu, a1, o);
        a2 += __shfl_down_sync(0xffffffffu, a2, o);
    }
    if (lane == 0) {
        float s0 = sigf(a0 + b3[0]);
        float s1 = sigf(a1 + b3[1]);
        float s2 = sigf(a2 + b3[2]);
        g_gates[(size_t)b * 3 + 0] = s0;
        g_gates[(size_t)b * 3 + 1] = s1;
        g_gates[(size_t)b * 3 + 2] = s2;
        atomicAdd(&sacc[0], s0);
        atomicAdd(&sacc[1], s1);
        atomicAdd(&sacc[2], s2);
    }
    __syncthreads();
    if (tid < 3) atomicAdd(&g_stats[tid], sacc[tid]);
}

// ---------------- m2[o] += sum_b fast[b,o]^2 ---------------------------------
__global__ __launch_bounds__(256)
void m2_kernel()
{
    const int c = threadIdx.x;
    const int r0 = blockIdx.x * 256;
    float s0 = 0.f, s1 = 0.f;
    for (int r = r0; r < r0 + 256; ++r) {
        float f0 = g_fast[(size_t)r * DOUT + c];
        float f1 = g_fast[(size_t)r * DOUT + c + 256];
        s0 = fmaf(f0, f0, s0);
        s1 = fmaf(f1, f1, s1);
    }
    atomicAdd(&g_m2[c], s0);
    atomicAdd(&g_m2[c + 256], s1);
}

// ---------------- combine + swish-beta + layernorm ---------------------------
__global__ __launch_bounds__(128)
void finalize_kernel(const float* __restrict__ gamma,
                     const float* __restrict__ lbeta,
                     float* __restrict__ outp)
{
    const int b = blockIdx.x;
    const int tid = threadIdx.x;
    const float sens = g_gates[(size_t)b * 3 + 1];
    const float gate = g_gates[(size_t)b * 3 + 2];
    const float be = 0.5f + 2.0f * sens;

    float a[4];
    float s = 0.f, sq = 0.f;
#pragma unroll
    for (int i = 0; i < 4; ++i) {
        const int c = tid + i * 128;
        float cmb = g_slow[(size_t)b * DOUT + c] + g_fast[(size_t)b * DOUT + c] * gate;
        float act = cmb * sigf(be * cmb);
        a[i] = act;
        s += act;
        sq = fmaf(act, act, sq);
    }

    __shared__ float sh[8];
#pragma unroll
    for (int o = 16; o > 0; o >>= 1) {
        s  += __shfl_down_sync(0xffffffffu, s,  o);
        sq += __shfl_down_sync(0xffffffffu, sq, o);
    }
    const int lane = tid & 31, warp = tid >> 5;
    if (lane == 0) { sh[warp] = s; sh[4 + warp] = sq; }
    __syncthreads();
    if (tid == 0) {
        sh[0] = sh[0] + sh[1] + sh[2] + sh[3];
        sh[4] = sh[4] + sh[5] + sh[6] + sh[7];
    }
    __syncthreads();
    const float mu  = sh[0] * (1.0f / DOUT);
    const float var = sh[4] * (1.0f / DOUT) - mu * mu;
    const float inv = rsqrtf(var + 1e-5f);
#pragma unroll
    for (int i = 0; i < 4; ++i) {
        const int c = tid + i * 128;
        outp[(size_t)b * DOUT + c] = (a[i] - mu) * inv * gamma[c] + lbeta[c];
    }
}

// ---------------- W_fast update + stats output -------------------------------
__global__ void wfast_kernel(const float* __restrict__ Wf,
                             float* __restrict__ out_wf,
                             float* __restrict__ out_st)
{
    const int o = blockIdx.x;
    const float rate = g_stats[0] * (0.1f / (float)BATCH);
    const float m2 = g_m2[o] * (1.0f / (float)BATCH);
    for (int d = threadIdx.x; d < DIN; d += blockDim.x) {
        const float wf = Wf[o * DIN + d];
        const float hebb = g_hebb[o * DIN + d] * (1.0f / (float)BATCH);
        out_wf[o * DIN + d] = wf + tanhf(hebb - m2 * wf) * rate;
    }
    if (o == 0 && threadIdx.x < 3)
        out_st[threadIdx.x] = g_stats[threadIdx.x] * (1.0f / (float)BATCH);
}

// ---------------- launch -----------------------------------------------------
extern "C" void kernel_launch(void* const* d_in, const int* in_sizes, int n_in,
                              void* d_out, int out_size)
{
    (void)in_sizes; (void)n_in; (void)out_size;

    const float* x      = (const float*)d_in[0];
    const int*   step   = (const int*)  d_in[1];
    const float* cms_w1 = (const float*)d_in[2];
    const float* cms_b1 = (const float*)d_in[3];
    const float* cms_w2 = (const float*)d_in[4];
    const float* cms_b2 = (const float*)d_in[5];
    const float* gmw    = (const float*)d_in[6];
    const float* gmb    = (const float*)d_in[7];
    const float* gsw    = (const float*)d_in[8];
    const float* gsb    = (const float*)d_in[9];
    const float* ggw    = (const float*)d_in[10];
    const float* ggb    = (const float*)d_in[11];
    const float* gow    = (const float*)d_in[12];
    const float* gob    = (const float*)d_in[13];
    const float* Wslow  = (const float*)d_in[14];
    const float* Wfast  = (const float*)d_in[15];
    const float* gamma  = (const float*)d_in[16];
    const float* lbeta  = (const float*)d_in[17];

    float* out    = (float*)d_out;
    float* out_ln = out;
    float* out_wf = out + (size_t)BATCH * DOUT;
    float* out_st = out_wf + DOUT * DIN;

    void* p;
    cudaGetSymbolAddress(&p, g_buf);  float* buf   = (float*)p;
    cudaGetSymbolAddress(&p, g_h);    float* hbuf  = (float*)p;
    cudaGetSymbolAddress(&p, g_slow); float* slow  = (float*)p;
    cudaGetSymbolAddress(&p, g_fast); float* fastb = (float*)p;
    cudaGetSymbolAddress(&p, g_w1r);  float* w1r   = (float*)p;
    cudaGetSymbolAddress(&p, g_w2r);  float* w2r   = (float*)p;
    cudaGetSymbolAddress(&p, g_gwr);  float* gwr   = (float*)p;
    cudaGetSymbolAddress(&p, g_sfr);  float* sfr   = (float*)p;

    const dim3 blk(256);
    const dim3 gh(HIDN / 128, BATCH / 128);  // N=1024 GEMMs
    const dim3 gd(DIN  / 128, BATCH / 128);  // N=512  GEMMs

    prep_kernel<<<512, 256>>>(cms_w1, cms_w2, gmw, gsw, ggw, Wslow, Wfast);

    // per-level weight stride is HIDN*DIN == DIN*HIDN == NGW
    // CMS level 0 (freq 1); A=x is fp32 -> CVTA; outputs rounded.
    mma_gemm<EPI_RELU , true , true ><<<gh, blk>>>(x,    w1r, cms_b1, nullptr, hbuf, HIDN, DIN,  step, 1);
    mma_gemm<EPI_RESID, false, true ><<<gd, blk>>>(hbuf, w2r, cms_b2, x,       buf,  DIN,  HIDN, step, 1);
    // CMS level 1 (freq 4)
    mma_gemm<EPI_RELU , false, true ><<<gh, blk>>>(buf,  w1r + NGW,     cms_b1 + HIDN,     nullptr, hbuf, HIDN, DIN,  step, 4);
    mma_gemm<EPI_RESID, false, true ><<<gd, blk>>>(hbuf, w2r + NGW,     cms_b2 + DIN,      buf,     buf,  DIN,  HIDN, step, 4);
    // CMS level 2 (freq 16)
    mma_gemm<EPI_RELU , false, true ><<<gh, blk>>>(buf,  w1r + 2 * NGW, cms_b1 + 2 * HIDN, nullptr, hbuf, HIDN, DIN,  step, 16);
    mma_gemm<EPI_RESID, false, true ><<<gd, blk>>>(hbuf, w2r + 2 * NGW, cms_b2 + 2 * DIN,  buf,     buf,  DIN,  HIDN, step, 16);

    // gate hidden sums (unrounded outputs: consumed by fp32 gateout)
    mma_gemm<EPI_SIGW, false, false><<<gh, blk>>>(buf, gwr,           gmb, nullptr, hbuf, HIDN, DIN, step, 1);
    mma_gemm<EPI_SIGA, false, false><<<gh, blk>>>(buf, gwr + NGW,     gsb, nullptr, hbuf, HIDN, DIN, step, 1);
    mma_gemm<EPI_SIGA, false, false><<<gh, blk>>>(buf, gwr + 2 * NGW, ggb, nullptr, hbuf, HIDN, DIN, step, 1);

    gateout_kernel<<<BATCH / 8, 256>>>(hbuf, gow, gob);

    // slow / fast projections (fp32 outputs for finalize)
    mma_gemm<EPI_NONE, false, false><<<gd, blk>>>(buf, sfr,       nullptr, nullptr, slow,  DOUT, DIN, step, 1);
    mma_gemm<EPI_NONE, false, false><<<gd, blk>>>(buf, sfr + NSF, nullptr, nullptr, fastb, DOUT, DIN, step, 1);

    hebb_mma_kernel<<<dim3(4, 4, 32), blk>>>();
    m2_kernel<<<BATCH / 256, 256>>>();

    finalize_kernel<<<BATCH, 128>>>(gamma, lbeta, out_ln);
    wfast_kernel<<<DOUT, 256>>>(Wfast, out_wf, out_st);
}

// round 5
// speedup vs baseline: 2.9339x; 1.0109x over previous
#include <cuda_runtime.h>
#include <math.h>
#include <stdint.h>

#define BATCH 65536
#define DIN   512
#define DOUT  512
#define HIDN  1024

// ---------------- scratch (static device globals; no allocation) -------------
__device__ float g_buf [(size_t)BATCH * DIN];
__device__ float g_h   [(size_t)BATCH * HIDN];
__device__ float g_slow[(size_t)BATCH * DOUT];
__device__ float g_fast[(size_t)BATCH * DOUT];
__device__ float g_gates[(size_t)BATCH * 3];
__device__ float g_hebb[DOUT * DIN];
__device__ float g_m2  [DOUT];
__device__ float g_stats[4];

// tf32-rounded weight copies
__device__ float g_w1r[3 * HIDN * DIN];
__device__ float g_w2r[3 * DIN * HIDN];
__device__ float g_gwr[3 * HIDN * DIN];
__device__ float g_sfr[2 * DOUT * DIN];

__device__ __forceinline__ float sigf(float x) { return 1.0f / (1.0f + expf(-x)); }

__device__ __forceinline__ uint32_t f2tf32(float x) {
    uint32_t r;
    asm("cvt.rna.tf32.f32 %0, %1;" : "=r"(r) : "f"(x));
    return r;
}
__device__ __forceinline__ float roundtf(float x) { return __uint_as_float(f2tf32(x)); }

__device__ __forceinline__ void mma_tf32(float* c, const uint32_t* a, const uint32_t* b) {
    asm volatile(
        "mma.sync.aligned.m16n8k8.row.col.f32.tf32.tf32.f32 "
        "{%0,%1,%2,%3}, {%4,%5,%6,%7}, {%8,%9}, {%0,%1,%2,%3};\n"
        : "+f"(c[0]), "+f"(c[1]), "+f"(c[2]), "+f"(c[3])
        : "r"(a[0]), "r"(a[1]), "r"(a[2]), "r"(a[3]), "r"(b[0]), "r"(b[1]));
}

__device__ __forceinline__ void cp16(void* smem, const void* g) {
    uint32_t s = (uint32_t)__cvta_generic_to_shared(smem);
    asm volatile("cp.async.cg.shared.global [%0], [%1], 16;\n" :: "r"(s), "l"(g));
}
__device__ __forceinline__ void cp_commit() { asm volatile("cp.async.commit_group;\n"); }
template <int N>
__device__ __forceinline__ void cp_wait() { asm volatile("cp.async.wait_group %0;\n" :: "n"(N)); }

// ---------------- prepass ----------------------------------------------------
#define NW1 (3 * HIDN * DIN)
#define NW2 (3 * DIN * HIDN)
#define NGW (HIDN * DIN)
#define NSF (DOUT * DIN)

__global__ void prep_kernel(const float* __restrict__ w1, const float* __restrict__ w2,
                            const float* __restrict__ gm, const float* __restrict__ gs,
                            const float* __restrict__ gg, const float* __restrict__ ws,
                            const float* __restrict__ wf)
{
    const int idx = blockIdx.x * blockDim.x + threadIdx.x;
    const int stride = gridDim.x * blockDim.x;
    for (int i = idx; i < NW1; i += stride) g_w1r[i] = roundtf(w1[i]);
    for (int i = idx; i < NW2; i += stride) g_w2r[i] = roundtf(w2[i]);
    for (int i = idx; i < NGW; i += stride) {
        g_gwr[i]           = roundtf(gm[i]);
        g_gwr[i + NGW]     = roundtf(gs[i]);
        g_gwr[i + 2 * NGW] = roundtf(gg[i]);
    }
    for (int i = idx; i < NSF; i += stride) {
        g_sfr[i]       = roundtf(ws[i]);
        g_sfr[i + NSF] = roundtf(wf[i]);
    }
    for (int i = idx; i < DOUT * DIN; i += stride) g_hebb[i] = 0.0f;
    if (idx < DOUT) g_m2[idx] = 0.0f;
    if (idx < 4)    g_stats[idx] = 0.0f;
}

// ---------------- tf32 tensor-core GEMM, 4-stage cp.async pipeline -----------
enum { EPI_RELU = 0, EPI_RESID = 1, EPI_SIGW = 2, EPI_SIGA = 3, EPI_NONE = 4 };

#define SPITCH 20
#define STAGES 4
#define GEMM_SMEM (STAGES * 2 * 128 * SPITCH * 4)   // 81920 bytes

// block tile 128x128x16; 8 warps as 2(M) x 4(N); warp tile 64x32.
template <int EPI, bool CVTA, bool ROUND_OUT>
__global__ __launch_bounds__(256, 2)
void mma_gemm(const float* __restrict__ A, const float* __restrict__ W,
              const float* __restrict__ bias, const float* __restrict__ R,
              float* __restrict__ C, int N, int K,
              const int* __restrict__ step, int freq)
{
    if (freq > 1) { if ((step[0] % freq) != 0) return; }

    extern __shared__ float dynsmem[];
    float (*As)[128][SPITCH] = (float(*)[128][SPITCH])dynsmem;
    float (*Bs)[128][SPITCH] = (float(*)[128][SPITCH])(dynsmem + STAGES * 128 * SPITCH);

    const int tid  = threadIdx.x;
    const int lane = tid & 31;
    const int warp = tid >> 5;
    const int wm   = warp >> 2;
    const int wn   = warp & 3;
    const int m0   = blockIdx.y * 128;
    const int n0   = blockIdx.x * 128;

    float acc[4][4][4];
#pragma unroll
    for (int mt = 0; mt < 4; ++mt)
#pragma unroll
        for (int nt = 0; nt < 4; ++nt)
#pragma unroll
            for (int i = 0; i < 4; ++i) acc[mt][nt][i] = 0.0f;

    const int lr = tid >> 2;   // 0..63
    const int lc = tid & 3;    // k-chunk (float4)

    const float* Ag = A + (size_t)(m0 + lr) * K + lc * 4;
    const float* Wg = W + (size_t)(n0 + lr) * K + lc * 4;

    const int KT = K >> 4;

    // prologue: prefetch stages 0..2
#pragma unroll
    for (int s = 0; s < STAGES - 1; ++s) {
        const size_t ko = (size_t)s * 16;
        cp16(&As[s][lr][lc * 4],      Ag + ko);
        cp16(&As[s][lr + 64][lc * 4], Ag + (size_t)64 * K + ko);
        cp16(&Bs[s][lr][lc * 4],      Wg + ko);
        cp16(&Bs[s][lr + 64][lc * 4], Wg + (size_t)64 * K + ko);
        cp_commit();
    }

    for (int kt = 0; kt < KT; ++kt) {
        cp_wait<STAGES - 2>();
        __syncthreads();            // stage kt ready; all warps done with stage kt-1

        if (kt + STAGES - 1 < KT) { // prefetch stage kt+3 into ring slot (kt-1)&3
            const int st = (kt + STAGES - 1) & (STAGES - 1);
            const size_t ko = (size_t)(kt + STAGES - 1) * 16;
            cp16(&As[st][lr][lc * 4],      Ag + ko);
            cp16(&As[st][lr + 64][lc * 4], Ag + (size_t)64 * K + ko);
            cp16(&Bs[st][lr][lc * 4],      Wg + ko);
            cp16(&Bs[st][lr + 64][lc * 4], Wg + (size_t)64 * K + ko);
        }
        cp_commit();                // empty group near the tail keeps wait counts aligned

        const int cur = kt & (STAGES - 1);
#pragma unroll
        for (int ks = 0; ks < 2; ++ks) {
            const int kk = ks * 8 + (lane & 3);
            uint32_t af[4][4];
#pragma unroll
            for (int mt = 0; mt < 4; ++mt) {
                const int mr = wm * 64 + mt * 16 + (lane >> 2);
                if (CVTA) {
                    af[mt][0] = f2tf32(As[cur][mr][kk]);
                    af[mt][1] = f2tf32(As[cur][mr + 8][kk]);
                    af[mt][2] = f2tf32(As[cur][mr][kk + 4]);
                    af[mt][3] = f2tf32(As[cur][mr + 8][kk + 4]);
                } else {
                    af[mt][0] = __float_as_uint(As[cur][mr][kk]);
                    af[mt][1] = __float_as_uint(As[cur][mr + 8][kk]);
                    af[mt][2] = __float_as_uint(As[cur][mr][kk + 4]);
                    af[mt][3] = __float_as_uint(As[cur][mr + 8][kk + 4]);
                }
            }
            uint32_t bf[4][2];
#pragma unroll
            for (int nt = 0; nt < 4; ++nt) {
                const int nc = wn * 32 + nt * 8 + (lane >> 2);
                bf[nt][0] = __float_as_uint(Bs[cur][nc][kk]);
                bf[nt][1] = __float_as_uint(Bs[cur][nc][kk + 4]);
            }
#pragma unroll
            for (int mt = 0; mt < 4; ++mt)
#pragma unroll
                for (int nt = 0; nt < 4; ++nt)
                    mma_tf32(acc[mt][nt], af[mt], bf[nt]);
        }
    }

    // epilogue
#pragma unroll
    for (int mt = 0; mt < 4; ++mt) {
#pragma unroll
        for (int nt = 0; nt < 4; ++nt) {
            const int col = n0 + wn * 32 + nt * 8 + (lane & 3) * 2;
            float bv0 = 0.f, bv1 = 0.f;
            if (EPI != EPI_NONE) { bv0 = bias[col]; bv1 = bias[col + 1]; }
#pragma unroll
            for (int h = 0; h < 2; ++h) {
                const int row = m0 + wm * 64 + mt * 16 + (lane >> 2) + h * 8;
                const size_t idx = (size_t)row * N + col;
                float v0 = acc[mt][nt][h * 2 + 0] + bv0;
                float v1 = acc[mt][nt][h * 2 + 1] + bv1;
                if (EPI == EPI_RELU) {
                    v0 = v0 > 0.f ? v0 : 0.f;
                    v1 = v1 > 0.f ? v1 : 0.f;
                } else if (EPI == EPI_RESID) {
                    v0 += R[idx]; v1 += R[idx + 1];
                } else if (EPI == EPI_SIGW) {
                    v0 = sigf(v0); v1 = sigf(v1);
                } else if (EPI == EPI_SIGA) {
                    v0 = C[idx] + sigf(v0); v1 = C[idx + 1] + sigf(v1);
                }
                if (ROUND_OUT) { v0 = roundtf(v0); v1 = roundtf(v1); }
                *(float2*)&C[idx] = make_float2(v0, v1);
            }
        }
    }
}

// ---------------- hebb: split-K tf32 GEMM, 4-stage pipeline ------------------
#define HPITCH 136
#define HEBB_SMEM (STAGES * 2 * 16 * HPITCH * 4)    // 69632 bytes

__global__ __launch_bounds__(256, 2)
void hebb_mma_kernel()
{
    extern __shared__ float dynsmem[];
    float (*Fs)[16][HPITCH] = (float(*)[16][HPITCH])dynsmem;
    float (*Xs)[16][HPITCH] = (float(*)[16][HPITCH])(dynsmem + STAGES * 16 * HPITCH);

    const int tid  = threadIdx.x;
    const int lane = tid & 31;
    const int warp = tid >> 5;
    const int wm   = warp >> 2;
    const int wn   = warp & 3;
    const int o0   = blockIdx.x * 128;
    const int d0   = blockIdx.y * 128;
    const int b0   = blockIdx.z * 2048;

    float acc[4][4][4];
#pragma unroll
    for (int mt = 0; mt < 4; ++mt)
#pragma unroll
        for (int nt = 0; nt < 4; ++nt)
#pragma unroll
            for (int i = 0; i < 4; ++i) acc[mt][nt][i] = 0.0f;

    const int r0 = tid >> 5,         c0 = tid & 31;
    const int r1 = (tid + 256) >> 5, c1 = tid & 31;

    const int KT = 2048 / 16;

#pragma unroll
    for (int s = 0; s < STAGES - 1; ++s) {
        const int bb = b0 + s * 16;
        cp16(&Fs[s][r0][c0 * 4], &g_fast[(size_t)(bb + r0) * DOUT + o0 + c0 * 4]);
        cp16(&Fs[s][r1][c1 * 4], &g_fast[(size_t)(bb + r1) * DOUT + o0 + c1 * 4]);
        cp16(&Xs[s][r0][c0 * 4], &g_buf [(size_t)(bb + r0) * DIN  + d0 + c0 * 4]);
        cp16(&Xs[s][r1][c1 * 4], &g_buf [(size_t)(bb + r1) * DIN  + d0 + c1 * 4]);
        cp_commit();
    }

    for (int kt = 0; kt < KT; ++kt) {
        cp_wait<STAGES - 2>();
        __syncthreads();

        if (kt + STAGES - 1 < KT) {
            const int st = (kt + STAGES - 1) & (STAGES - 1);
            const int bb = b0 + (kt + STAGES - 1) * 16;
            cp16(&Fs[st][r0][c0 * 4], &g_fast[(size_t)(bb + r0) * DOUT + o0 + c0 * 4]);
            cp16(&Fs[st][r1][c1 * 4], &g_fast[(size_t)(bb + r1) * DOUT + o0 + c1 * 4]);
            cp16(&Xs[st][r0][c0 * 4], &g_buf [(size_t)(bb + r0) * DIN  + d0 + c0 * 4]);
            cp16(&Xs[st][r1][c1 * 4], &g_buf [(size_t)(bb + r1) * DIN  + d0 + c1 * 4]);
        }
        cp_commit();

        const int cur = kt & (STAGES - 1);
#pragma unroll
        for (int ks = 0; ks < 2; ++ks) {
            const int kk = ks * 8 + (lane & 3);
            uint32_t af[4][4];
#pragma unroll
            for (int mt = 0; mt < 4; ++mt) {
                const int mr = wm * 64 + mt * 16 + (lane >> 2);
                af[mt][0] = f2tf32(Fs[cur][kk][mr]);
                af[mt][1] = f2tf32(Fs[cur][kk][mr + 8]);
                af[mt][2] = f2tf32(Fs[cur][kk + 4][mr]);
                af[mt][3] = f2tf32(Fs[cur][kk + 4][mr + 8]);
            }
            uint32_t bf[4][2];
#pragma unroll
            for (int nt = 0; nt < 4; ++nt) {
                const int nc = wn * 32 + nt * 8 + (lane >> 2);
                bf[nt][0] = __float_as_uint(Xs[cur][kk][nc]);
                bf[nt][1] = __float_as_uint(Xs[cur][kk + 4][nc]);
            }
#pragma unroll
            for (int mt = 0; mt < 4; ++mt)
#pragma unroll
                for (int nt = 0; nt < 4; ++nt)
                    mma_tf32(acc[mt][nt], af[mt], bf[nt]);
        }
    }

#pragma unroll
    for (int mt = 0; mt < 4; ++mt)
#pragma unroll
        for (int nt = 0; nt < 4; ++nt) {
            const int col = d0 + wn * 32 + nt * 8 + (lane & 3) * 2;
#pragma unroll
            for (int h = 0; h < 2; ++h) {
                const int row = o0 + wm * 64 + mt * 16 + (lane >> 2) + h * 8;
                atomicAdd(&g_hebb[row * DIN + col],     acc[mt][nt][h * 2 + 0]);
                atomicAdd(&g_hebb[row * DIN + col + 1], acc[mt][nt][h * 2 + 1]);
            }
        }
}

// ---------------- gates head --------------------------------------------------
__global__ __launch_bounds__(256)
void gateout_kernel(const float* __restrict__ gsum,
                    const float* __restrict__ w,
                    const float* __restrict__ b3)
{
    __shared__ float sw[3 * HIDN];
    __shared__ float sacc[3];
    const int tid = threadIdx.x;
    for (int i = tid; i < 3 * HIDN; i += 256) sw[i] = w[i];
    if (tid < 3) sacc[tid] = 0.0f;
    __syncthreads();

    const int lane = tid & 31, warp = tid >> 5;
    const int b = blockIdx.x * 8 + warp;
    const float* row = gsum + (size_t)b * HIDN;
    float a0 = 0.f, a1 = 0.f, a2 = 0.f;
    for (int h = lane; h < HIDN; h += 32) {
        float v = row[h];
        a0 = fmaf(v, sw[h],            a0);
        a1 = fmaf(v, sw[HIDN + h],     a1);
        a2 = fmaf(v, sw[2 * HIDN + h], a2);
    }
#pragma unroll
    for (int o = 16; o > 0; o >>= 1) {
        a0 += __shfl_down_sync(0xffffffffu, a0, o);
        a1 += __shfl_down_sync(0xffffffffu, a1, o);
        a2 += __shfl_down_sync(0xffffffffu, a2, o);
    }
    if (lane == 0) {
        float s0 = sigf(a0 + b3[0]);
        float s1 = sigf(a1 + b3[1]);
        float s2 = sigf(a2 + b3[2]);
        g_gates[(size_t)b * 3 + 0] = s0;
        g_gates[(size_t)b * 3 + 1] = s1;
        g_gates[(size_t)b * 3 + 2] = s2;
        atomicAdd(&sacc[0], s0);
        atomicAdd(&sacc[1], s1);
        atomicAdd(&sacc[2], s2);
    }
    __syncthreads();
    if (tid < 3) atomicAdd(&g_stats[tid], sacc[tid]);
}

// ---------------- m2 -----------------------------------------------------------
__global__ __launch_bounds__(256)
void m2_kernel()
{
    const int c = threadIdx.x;
    const int r0 = blockIdx.x * 256;
    float s0 = 0.f, s1 = 0.f;
    for (int r = r0; r < r0 + 256; ++r) {
        float f0 = g_fast[(size_t)r * DOUT + c];
        float f1 = g_fast[(size_t)r * DOUT + c + 256];
        s0 = fmaf(f0, f0, s0);
        s1 = fmaf(f1, f1, s1);
    }
    atomicAdd(&g_m2[c], s0);
    atomicAdd(&g_m2[c + 256], s1);
}

// ---------------- combine + swish-beta + layernorm ---------------------------
__global__ __launch_bounds__(128)
void finalize_kernel(const float* __restrict__ gamma,
                     const float* __restrict__ lbeta,
                     float* __restrict__ outp)
{
    const int b = blockIdx.x;
    const int tid = threadIdx.x;
    const float sens = g_gates[(size_t)b * 3 + 1];
    const float gate = g_gates[(size_t)b * 3 + 2];
    const float be = 0.5f + 2.0f * sens;

    float a[4];
    float s = 0.f, sq = 0.f;
#pragma unroll
    for (int i = 0; i < 4; ++i) {
        const int c = tid + i * 128;
        float cmb = g_slow[(size_t)b * DOUT + c] + g_fast[(size_t)b * DOUT + c] * gate;
        float act = cmb * sigf(be * cmb);
        a[i] = act;
        s += act;
        sq = fmaf(act, act, sq);
    }

    __shared__ float sh[8];
#pragma unroll
    for (int o = 16; o > 0; o >>= 1) {
        s  += __shfl_down_sync(0xffffffffu, s,  o);
        sq += __shfl_down_sync(0xffffffffu, sq, o);
    }
    const int lane = tid & 31, warp = tid >> 5;
    if (lane == 0) { sh[warp] = s; sh[4 + warp] = sq; }
    __syncthreads();
    if (tid == 0) {
        sh[0] = sh[0] + sh[1] + sh[2] + sh[3];
        sh[4] = sh[4] + sh[5] + sh[6] + sh[7];
    }
    __syncthreads();
    const float mu  = sh[0] * (1.0f / DOUT);
    const float var = sh[4] * (1.0f / DOUT) - mu * mu;
    const float inv = rsqrtf(var + 1e-5f);
#pragma unroll
    for (int i = 0; i < 4; ++i) {
        const int c = tid + i * 128;
        outp[(size_t)b * DOUT + c] = (a[i] - mu) * inv * gamma[c] + lbeta[c];
    }
}

// ---------------- W_fast update + stats output -------------------------------
__global__ void wfast_kernel(const float* __restrict__ Wf,
                             float* __restrict__ out_wf,
                             float* __restrict__ out_st)
{
    const int o = blockIdx.x;
    const float rate = g_stats[0] * (0.1f / (float)BATCH);
    const float m2 = g_m2[o] * (1.0f / (float)BATCH);
    for (int d = threadIdx.x; d < DIN; d += blockDim.x) {
        const float wf = Wf[o * DIN + d];
        const float hebb = g_hebb[o * DIN + d] * (1.0f / (float)BATCH);
        out_wf[o * DIN + d] = wf + tanhf(hebb - m2 * wf) * rate;
    }
    if (o == 0 && threadIdx.x < 3)
        out_st[threadIdx.x] = g_stats[threadIdx.x] * (1.0f / (float)BATCH);
}

// ---------------- launch -----------------------------------------------------
extern "C" void kernel_launch(void* const* d_in, const int* in_sizes, int n_in,
                              void* d_out, int out_size)
{
    (void)in_sizes; (void)n_in; (void)out_size;

    const float* x      = (const float*)d_in[0];
    const int*   step   = (const int*)  d_in[1];
    const float* cms_w1 = (const float*)d_in[2];
    const float* cms_b1 = (const float*)d_in[3];
    const float* cms_w2 = (const float*)d_in[4];
    const float* cms_b2 = (const float*)d_in[5];
    const float* gmw    = (const float*)d_in[6];
    const float* gmb    = (const float*)d_in[7];
    const float* gsw    = (const float*)d_in[8];
    const float* gsb    = (const float*)d_in[9];
    const float* ggw    = (const float*)d_in[10];
    const float* ggb    = (const float*)d_in[11];
    const float* gow    = (const float*)d_in[12];
    const float* gob    = (const float*)d_in[13];
    const float* Wslow  = (const float*)d_in[14];
    const float* Wfast  = (const float*)d_in[15];
    const float* gamma  = (const float*)d_in[16];
    const float* lbeta  = (const float*)d_in[17];

    float* out    = (float*)d_out;
    float* out_ln = out;
    float* out_wf = out + (size_t)BATCH * DOUT;
    float* out_st = out_wf + DOUT * DIN;

    void* p;
    cudaGetSymbolAddress(&p, g_buf);  float* buf   = (float*)p;
    cudaGetSymbolAddress(&p, g_h);    float* hbuf  = (float*)p;
    cudaGetSymbolAddress(&p, g_slow); float* slow  = (float*)p;
    cudaGetSymbolAddress(&p, g_fast); float* fastb = (float*)p;
    cudaGetSymbolAddress(&p, g_w1r);  float* w1r   = (float*)p;
    cudaGetSymbolAddress(&p, g_w2r);  float* w2r   = (float*)p;
    cudaGetSymbolAddress(&p, g_gwr);  float* gwr   = (float*)p;
    cudaGetSymbolAddress(&p, g_sfr);  float* sfr   = (float*)p;

    // opt-in to >48KB dynamic smem (host-side attribute set; capture-legal)
    static bool attr_done = false;
    if (!attr_done) {
        cudaFuncSetAttribute(mma_gemm<EPI_RELU , true , true >, cudaFuncAttributeMaxDynamicSharedMemorySize, GEMM_SMEM);
        cudaFuncSetAttribute(mma_gemm<EPI_RESID, false, true >, cudaFuncAttributeMaxDynamicSharedMemorySize, GEMM_SMEM);
        cudaFuncSetAttribute(mma_gemm<EPI_RELU , false, true >, cudaFuncAttributeMaxDynamicSharedMemorySize, GEMM_SMEM);
        cudaFuncSetAttribute(mma_gemm<EPI_SIGW , false, false>, cudaFuncAttributeMaxDynamicSharedMemorySize, GEMM_SMEM);
        cudaFuncSetAttribute(mma_gemm<EPI_SIGA , false, false>, cudaFuncAttributeMaxDynamicSharedMemorySize, GEMM_SMEM);
        cudaFuncSetAttribute(mma_gemm<EPI_NONE , false, false>, cudaFuncAttributeMaxDynamicSharedMemorySize, GEMM_SMEM);
        cudaFuncSetAttribute(hebb_mma_kernel,                   cudaFuncAttributeMaxDynamicSharedMemorySize, HEBB_SMEM);
        attr_done = true;
    }

    const dim3 blk(256);
    const dim3 gh(HIDN / 128, BATCH / 128);
    const dim3 gd(DIN  / 128, BATCH / 128);

    prep_kernel<<<512, 256>>>(cms_w1, cms_w2, gmw, gsw, ggw, Wslow, Wfast);

    // CMS level 0 (freq 1); A=x is fp32 -> CVTA; outputs rounded.
    mma_gemm<EPI_RELU , true , true ><<<gh, blk, GEMM_SMEM>>>(x,    w1r, cms_b1, nullptr, hbuf, HIDN, DIN,  step, 1);
    mma_gemm<EPI_RESID, false, true ><<<gd, blk, GEMM_SMEM>>>(hbuf, w2r, cms_b2, x,       buf,  DIN,  HIDN, step, 1);
    // CMS level 1 (freq 4)
    mma_gemm<EPI_RELU , false, true ><<<gh, blk, GEMM_SMEM>>>(buf,  w1r + NGW,     cms_b1 + HIDN,     nullptr, hbuf, HIDN, DIN,  step, 4);
    mma_gemm<EPI_RESID, false, true ><<<gd, blk, GEMM_SMEM>>>(hbuf, w2r + NGW,     cms_b2 + DIN,      buf,     buf,  DIN,  HIDN, step, 4);
    // CMS level 2 (freq 16)
    mma_gemm<EPI_RELU , false, true ><<<gh, blk, GEMM_SMEM>>>(buf,  w1r + 2 * NGW, cms_b1 + 2 * HIDN, nullptr, hbuf, HIDN, DIN,  step, 16);
    mma_gemm<EPI_RESID, false, true ><<<gd, blk, GEMM_SMEM>>>(hbuf, w2r + 2 * NGW, cms_b2 + 2 * DIN,  buf,     buf,  DIN,  HIDN, step, 16);

    // gate hidden sums
    mma_gemm<EPI_SIGW, false, false><<<gh, blk, GEMM_SMEM>>>(buf, gwr,           gmb, nullptr, hbuf, HIDN, DIN, step, 1);
    mma_gemm<EPI_SIGA, false, false><<<gh, blk, GEMM_SMEM>>>(buf, gwr + NGW,     gsb, nullptr, hbuf, HIDN, DIN, step, 1);
    mma_gemm<EPI_SIGA, false, false><<<gh, blk, GEMM_SMEM>>>(buf, gwr + 2 * NGW, ggb, nullptr, hbuf, HIDN, DIN, step, 1);

    gateout_kernel<<<BATCH / 8, 256>>>(hbuf, gow, gob);

    // slow / fast projections
    mma_gemm<EPI_NONE, false, false><<<gd, blk, GEMM_SMEM>>>(buf, sfr,       nullptr, nullptr, slow,  DOUT, DIN, step, 1);
    mma_gemm<EPI_NONE, false, false><<<gd, blk, GEMM_SMEM>>>(buf, sfr + NSF, nullptr, nullptr, fastb, DOUT, DIN, step, 1);

    hebb_mma_kernel<<<dim3(4, 4, 32), blk, HEBB_SMEM>>>();
    m2_kernel<<<BATCH / 256, 256>>>();

    finalize_kernel<<<BATCH, 128>>>(gamma, lbeta, out_ln);
    wfast_kernel<<<DOUT, 256>>>(Wfast, out_wf, out_st);
}